// round 1
// baseline (speedup 1.0000x reference)
#include <cuda_runtime.h>
#include <cstdint>
#include <cstddef>

#define T_STEPS 2048
#define BATCH   32
#define DIM     512
#define HID     512
#define GATES   2048   // 4*HID

// 512 MB scratch for gx = x @ w_ih^T + b_ih + b_hh  (zero-init .bss, no runtime alloc)
__device__ float g_gx[134217728];  // T_STEPS*BATCH*GATES

// global sense-reversing barrier state
__device__ unsigned int g_bar_count = 0;
__device__ unsigned int g_bar_gen   = 0;

// ---------------------------------------------------------------------------
// Kernel 1: gx[r][n] = sum_k X[r][k]*W[n][k] + bih[n] + bhh[n]
//   X = x viewed as [65536, 512], W = w_ih [2048, 512]
//   128x128 tile, 8x8 microtile, K-slab of 8.
// ---------------------------------------------------------------------------
__global__ void __launch_bounds__(256, 2) gemm_gx(
    const float* __restrict__ X,
    const float* __restrict__ W,
    const float* __restrict__ bih,
    const float* __restrict__ bhh)
{
    __shared__ float As[8][128];
    __shared__ float Bs[8][128];

    const int bm  = blockIdx.y * 128;
    const int bn  = blockIdx.x * 128;
    const int tid = threadIdx.x;
    const int tx  = tid & 15;
    const int ty  = tid >> 4;

    float acc[8][8];
#pragma unroll
    for (int i = 0; i < 8; i++)
#pragma unroll
        for (int j = 0; j < 8; j++) acc[i][j] = 0.f;

    const int lr = tid >> 1;         // 0..127
    const int lk = (tid & 1) * 4;    // 0 or 4
    const float* Ap = X + (size_t)(bm + lr) * DIM + lk;
    const float* Bp = W + (size_t)(bn + lr) * DIM + lk;

    for (int k0 = 0; k0 < DIM; k0 += 8) {
        float4 av = *(const float4*)(Ap + k0);
        float4 bv = *(const float4*)(Bp + k0);
        __syncthreads();
        As[lk + 0][lr] = av.x; As[lk + 1][lr] = av.y;
        As[lk + 2][lr] = av.z; As[lk + 3][lr] = av.w;
        Bs[lk + 0][lr] = bv.x; Bs[lk + 1][lr] = bv.y;
        Bs[lk + 2][lr] = bv.z; Bs[lk + 3][lr] = bv.w;
        __syncthreads();
#pragma unroll
        for (int kk = 0; kk < 8; kk++) {
            float a[8], b[8];
            *(float4*)&a[0] = *(const float4*)&As[kk][ty * 8];
            *(float4*)&a[4] = *(const float4*)&As[kk][ty * 8 + 4];
            *(float4*)&b[0] = *(const float4*)&Bs[kk][tx * 8];
            *(float4*)&b[4] = *(const float4*)&Bs[kk][tx * 8 + 4];
#pragma unroll
            for (int i = 0; i < 8; i++)
#pragma unroll
                for (int j = 0; j < 8; j++)
                    acc[i][j] = fmaf(a[i], b[j], acc[i][j]);
        }
    }

    const int row0 = bm + ty * 8;
    const int col0 = bn + tx * 8;
    float bias[8];
#pragma unroll
    for (int j = 0; j < 8; j++) bias[j] = bih[col0 + j] + bhh[col0 + j];

#pragma unroll
    for (int i = 0; i < 8; i++) {
        float4 v0, v1;
        v0.x = acc[i][0] + bias[0]; v0.y = acc[i][1] + bias[1];
        v0.z = acc[i][2] + bias[2]; v0.w = acc[i][3] + bias[3];
        v1.x = acc[i][4] + bias[4]; v1.y = acc[i][5] + bias[5];
        v1.z = acc[i][6] + bias[6]; v1.w = acc[i][7] + bias[7];
        float* dst = &g_gx[(size_t)(row0 + i) * GATES + col0];
        *(float4*)dst       = v0;
        *(float4*)(dst + 4) = v1;
    }
}

// ---------------------------------------------------------------------------
// Kernel 2: persistent recurrence. 128 blocks x 256 threads, 1 block/SM
// (forced by 118KB smem => all co-resident => global barrier is safe).
// Block owns 4 hidden units => 16 gate columns. w_hh slice lives in smem
// for all 2048 steps. h_{t-1} copied to smem (transposed, pad 33) each step.
// ---------------------------------------------------------------------------
#define RBLK 128
#define RTHR 256
// smem floats: WT[512*16]=8192 | HT[512*33]=16896 | RED[8*544]=4352 | CS[128]
#define SMEM_FLOATS (8192 + 16896 + 4352 + 128)

__device__ __forceinline__ void grid_barrier()
{
    __syncthreads();
    if (threadIdx.x == 0) {
        unsigned int gen = atomicAdd(&g_bar_gen, 0u);
        __threadfence();
        if (atomicAdd(&g_bar_count, 1u) == RBLK - 1) {
            atomicExch(&g_bar_count, 0u);
            __threadfence();
            atomicAdd(&g_bar_gen, 1u);
        } else {
            while (atomicAdd(&g_bar_gen, 0u) == gen) __nanosleep(64);
        }
        __threadfence();
    }
    __syncthreads();
}

__global__ void __launch_bounds__(RTHR, 1) lstm_rec(
    const float* __restrict__ h0, const float* __restrict__ c0,
    const float* __restrict__ whh,
    float* __restrict__ out, float* __restrict__ hn, float* __restrict__ cn)
{
    extern __shared__ float sm[];
    float* WT  = sm;             // [k:512][c:16]
    float* HT  = sm + 8192;      // [k:512][b:32] pad 33
    float* RED = HT + 16896;     // [ks:8][b*17+c] pad 544
    float* CS  = RED + 4352;     // [bb*4+uu]

    const int tid = threadIdx.x;
    const int u0  = blockIdx.x * 4;

    // load w_hh slice: local col c = uu*4+gate <-> global row gate*512 + u0+uu
    for (int idx = tid; idx < 8192; idx += RTHR) {
        int c    = idx & 15;
        int k    = idx >> 4;
        int uu   = c >> 2;
        int gate = c & 3;
        int grow = gate * HID + u0 + uu;
        WT[idx] = whh[(size_t)grow * HID + k];
    }
    if (tid < 128) {
        int bb = tid >> 2, uu = tid & 3;
        CS[bb * 4 + uu] = c0[bb * HID + u0 + uu];
    }
    __syncthreads();

    const int b   = tid & 31;   // batch lane for GEMM
    const int ks  = tid >> 5;   // K-slice 0..7
    const int ebb = tid & 31;   // epilogue batch
    const int euu = tid >> 5;   // epilogue unit (valid for tid<128)

    for (int t = 0; t < T_STEPS; t++) {
        const float* hsrc = (t == 0) ? h0 : (out + (size_t)(t - 1) * BATCH * HID);
        // copy h_{t-1} -> HT transposed [k][b] (pad 33, conflict-free)
        for (int i = tid; i < BATCH * HID; i += RTHR) {
            int bb = i >> 9;
            int kk = i & 511;
            HT[kk * 33 + bb] = hsrc[i];
        }
        // prefetch gx for this step (hides DRAM latency behind FMA loop)
        float gxv[4];
        if (tid < 128) {
            const size_t base = ((size_t)t * BATCH + ebb) * GATES;
#pragma unroll
            for (int g = 0; g < 4; g++)
                gxv[g] = g_gx[base + g * HID + (u0 + euu)];
        }
        __syncthreads();

        float acc[16];
#pragma unroll
        for (int c = 0; c < 16; c++) acc[c] = 0.f;

        const float*  hp = HT + (ks * 64) * 33 + b;
        const float4* wp = (const float4*)(WT + (ks * 64) * 16);
#pragma unroll 8
        for (int k = 0; k < 64; k++) {
            float hv = *hp; hp += 33;
            float4 w0 = wp[0], w1 = wp[1], w2 = wp[2], w3 = wp[3];
            wp += 4;
            acc[0]  = fmaf(hv, w0.x, acc[0]);
            acc[1]  = fmaf(hv, w0.y, acc[1]);
            acc[2]  = fmaf(hv, w0.z, acc[2]);
            acc[3]  = fmaf(hv, w0.w, acc[3]);
            acc[4]  = fmaf(hv, w1.x, acc[4]);
            acc[5]  = fmaf(hv, w1.y, acc[5]);
            acc[6]  = fmaf(hv, w1.z, acc[6]);
            acc[7]  = fmaf(hv, w1.w, acc[7]);
            acc[8]  = fmaf(hv, w2.x, acc[8]);
            acc[9]  = fmaf(hv, w2.y, acc[9]);
            acc[10] = fmaf(hv, w2.z, acc[10]);
            acc[11] = fmaf(hv, w2.w, acc[11]);
            acc[12] = fmaf(hv, w3.x, acc[12]);
            acc[13] = fmaf(hv, w3.y, acc[13]);
            acc[14] = fmaf(hv, w3.z, acc[14]);
            acc[15] = fmaf(hv, w3.w, acc[15]);
        }
        {
            float* rp = RED + ks * 544 + b * 17;
#pragma unroll
            for (int c = 0; c < 16; c++) rp[c] = acc[c];
        }
        __syncthreads();

        if (tid < 128) {
            float s0 = 0.f, s1 = 0.f, s2 = 0.f, s3 = 0.f;
            const float* q = RED + ebb * 17 + euu * 4;
#pragma unroll
            for (int kq = 0; kq < 8; kq++) {
                s0 += q[0]; s1 += q[1]; s2 += q[2]; s3 += q[3];
                q += 544;
            }
            float iv = s0 + gxv[0];
            float fv = s1 + gxv[1];
            float gv = s2 + gxv[2];
            float ov = s3 + gxv[3];
            float it = 1.f / (1.f + __expf(-iv));
            float ft = 1.f / (1.f + __expf(-fv));
            float gt = tanhf(gv);
            float ot = 1.f / (1.f + __expf(-ov));
            float cc  = CS[ebb * 4 + euu];
            float cnv = ft * cc + it * gt;
            CS[ebb * 4 + euu] = cnv;
            float hv = ot * tanhf(cnv);
            const int uo = u0 + euu;
            out[(size_t)t * BATCH * HID + ebb * HID + uo] = hv;
            if (t == T_STEPS - 1) {
                hn[ebb * HID + uo] = hv;
                cn[ebb * HID + uo] = cnv;
            }
        }
        grid_barrier();
    }
}

// ---------------------------------------------------------------------------
extern "C" void kernel_launch(void* const* d_in, const int* in_sizes, int n_in,
                              void* d_out, int out_size)
{
    const float* x   = (const float*)d_in[0];
    const float* h0  = (const float*)d_in[1];
    const float* c0  = (const float*)d_in[2];
    const float* wih = (const float*)d_in[3];
    const float* bih = (const float*)d_in[4];
    const float* whh = (const float*)d_in[5];
    const float* bhh = (const float*)d_in[6];

    float* out = (float*)d_out;
    float* hn  = out + (size_t)T_STEPS * BATCH * HID;
    float* cn  = hn + BATCH * HID;

    // 1) input projection for all timesteps
    gemm_gx<<<dim3(GATES / 128, (T_STEPS * BATCH) / 128), 256>>>(x, wih, bih, bhh);

    // 2) persistent recurrence (one launch, internal grid barrier per step)
    const size_t shmem = SMEM_FLOATS * sizeof(float);
    cudaFuncSetAttribute(lstm_rec, cudaFuncAttributeMaxDynamicSharedMemorySize, (int)shmem);
    lstm_rec<<<RBLK, RTHR, shmem>>>(h0, c0, whh, out, hn, cn);
}

// round 2
// speedup vs baseline: 1.0070x; 1.0070x over previous
#include <cuda_runtime.h>
#include <cstdint>
#include <cstddef>

#define T_STEPS 2048
#define BATCH   32
#define DIM     512
#define HID     512
#define GATES   2048   // 4*HID

typedef unsigned long long ull;

// 512 MB scratch for gx = x @ w_ih^T + b_ih + b_hh
__device__ float g_gx[134217728];  // T_STEPS*BATCH*GATES

// global sense-reversing barrier state
__device__ unsigned int g_bar_count = 0;
__device__ unsigned int g_bar_gen   = 0;

// ---------------- packed f32x2 helpers (Blackwell FFMA2 path) ----------------
__device__ __forceinline__ void ffma2(ull& d, ull a, ull b) {
    asm("fma.rn.f32x2 %0, %1, %2, %0;" : "+l"(d) : "l"(a), "l"(b));
}
__device__ __forceinline__ ull addf2(ull a, ull b) {
    ull r; asm("add.rn.f32x2 %0, %1, %2;" : "=l"(r) : "l"(a), "l"(b)); return r;
}
__device__ __forceinline__ ull pk2(float x, float y) {
    ull r; asm("mov.b64 %0, {%1, %2};" : "=l"(r) : "f"(x), "f"(y)); return r;
}
__device__ __forceinline__ float2 upk(ull v) {
    float2 r; asm("mov.b64 {%0, %1}, %2;" : "=f"(r.x), "=f"(r.y) : "l"(v)); return r;
}

// ---------------------------------------------------------------------------
// Kernel 1: gx[r][n] = sum_k X[r][k]*W[n][k] + bih[n] + bhh[n]
//   128x128 tile, 8x8 microtile via FFMA2, K-slab 8, double-buffered smem.
// ---------------------------------------------------------------------------
__global__ void __launch_bounds__(256, 2) gemm_gx(
    const float* __restrict__ X,
    const float* __restrict__ W,
    const float* __restrict__ bih,
    const float* __restrict__ bhh)
{
    __shared__ float As[2][8][128];
    __shared__ float Bs[2][8][128];

    const int bm  = blockIdx.y * 128;
    const int bn  = blockIdx.x * 128;
    const int tid = threadIdx.x;
    const int tx  = tid & 15;
    const int ty  = tid >> 4;

    // acc2[i2][j]: rows (ty*8+2*i2, ty*8+2*i2+1), col (tx*8+j)
    ull acc2[4][8];
#pragma unroll
    for (int i = 0; i < 4; i++)
#pragma unroll
        for (int j = 0; j < 8; j++) acc2[i][j] = 0ull;

    const int lr = tid >> 1;         // 0..127
    const int lk = (tid & 1) * 4;    // 0 or 4
    const float* Ap = X + (size_t)(bm + lr) * DIM + lk;
    const float* Bp = W + (size_t)(bn + lr) * DIM + lk;

    // preload slab 0
    {
        float4 av = *(const float4*)Ap;
        float4 bv = *(const float4*)Bp;
        As[0][lk + 0][lr] = av.x; As[0][lk + 1][lr] = av.y;
        As[0][lk + 2][lr] = av.z; As[0][lk + 3][lr] = av.w;
        Bs[0][lk + 0][lr] = bv.x; Bs[0][lk + 1][lr] = bv.y;
        Bs[0][lk + 2][lr] = bv.z; Bs[0][lk + 3][lr] = bv.w;
    }
    __syncthreads();

    const int NSLAB = DIM / 8;  // 64
    for (int s = 0; s < NSLAB; s++) {
        const int buf = s & 1;
        float4 avn, bvn;
        if (s + 1 < NSLAB) {
            avn = *(const float4*)(Ap + (s + 1) * 8);
            bvn = *(const float4*)(Bp + (s + 1) * 8);
        }
#pragma unroll
        for (int kk = 0; kk < 8; kk++) {
            // row pairs come pre-packed from smem
            const ulonglong2* a01 = (const ulonglong2*)&As[buf][kk][ty * 8];
            ulonglong2 al = a01[0];
            ulonglong2 ah = a01[1];
            ull a2[4] = { al.x, al.y, ah.x, ah.y };
            float4 b0 = *(const float4*)&Bs[buf][kk][tx * 8];
            float4 b1 = *(const float4*)&Bs[buf][kk][tx * 8 + 4];
            ull bd[8] = { pk2(b0.x, b0.x), pk2(b0.y, b0.y),
                          pk2(b0.z, b0.z), pk2(b0.w, b0.w),
                          pk2(b1.x, b1.x), pk2(b1.y, b1.y),
                          pk2(b1.z, b1.z), pk2(b1.w, b1.w) };
#pragma unroll
            for (int i2 = 0; i2 < 4; i2++)
#pragma unroll
                for (int j = 0; j < 8; j++)
                    ffma2(acc2[i2][j], a2[i2], bd[j]);
        }
        if (s + 1 < NSLAB) {
            const int nb = buf ^ 1;
            As[nb][lk + 0][lr] = avn.x; As[nb][lk + 1][lr] = avn.y;
            As[nb][lk + 2][lr] = avn.z; As[nb][lk + 3][lr] = avn.w;
            Bs[nb][lk + 0][lr] = bvn.x; Bs[nb][lk + 1][lr] = bvn.y;
            Bs[nb][lk + 2][lr] = bvn.z; Bs[nb][lk + 3][lr] = bvn.w;
            __syncthreads();
        }
    }

    const int row0 = bm + ty * 8;
    const int col0 = bn + tx * 8;
    float bias[8];
#pragma unroll
    for (int j = 0; j < 8; j++) bias[j] = bih[col0 + j] + bhh[col0 + j];

#pragma unroll
    for (int i = 0; i < 8; i++) {
        const int i2 = i >> 1;
        const int s  = i & 1;
        float v[8];
#pragma unroll
        for (int j = 0; j < 8; j++) {
            float2 p = upk(acc2[i2][j]);
            v[j] = (s ? p.y : p.x) + bias[j];
        }
        float* dst = &g_gx[(size_t)(row0 + i) * GATES + col0];
        float4 v0 = { v[0], v[1], v[2], v[3] };
        float4 v1 = { v[4], v[5], v[6], v[7] };
        *(float4*)dst       = v0;
        *(float4*)(dst + 4) = v1;
    }
}

// ---------------------------------------------------------------------------
// Kernel 2: persistent recurrence. 128 blocks x 256 threads, 1 block/SM.
// ---------------------------------------------------------------------------
#define RBLK 128
#define RTHR 256
// smem floats: WT[512*16]=8192 | HT[512*33]=16896 | RED[8*576]=4608 | CS[128]
#define SMEM_FLOATS (8192 + 16896 + 4608 + 128)

__device__ __forceinline__ void grid_barrier()
{
    __syncthreads();
    if (threadIdx.x == 0) {
        unsigned int gen = atomicAdd(&g_bar_gen, 0u);
        __threadfence();
        if (atomicAdd(&g_bar_count, 1u) == RBLK - 1) {
            atomicExch(&g_bar_count, 0u);
            __threadfence();
            atomicAdd(&g_bar_gen, 1u);
        } else {
            while (atomicAdd(&g_bar_gen, 0u) == gen) __nanosleep(64);
        }
        __threadfence();
    }
    __syncthreads();
}

__global__ void __launch_bounds__(RTHR, 1) lstm_rec(
    const float* __restrict__ h0, const float* __restrict__ c0,
    const float* __restrict__ whh,
    float* __restrict__ out, float* __restrict__ hn, float* __restrict__ cn)
{
    extern __shared__ float sm[];
    float* WT  = sm;             // [k:512][c:16]
    float* HT  = sm + 8192;      // [k:512][b:32] pad 33
    float* RED = HT + 16896;     // [ks:8][b*18 + c] pad 18 (8B-aligned pairs)
    float* CS  = RED + 4608;     // [bb*4+uu]

    const int tid = threadIdx.x;
    const int u0  = blockIdx.x * 4;

    // load w_hh slice: local col c = uu*4+gate <-> global row gate*512 + u0+uu
    for (int idx = tid; idx < 8192; idx += RTHR) {
        int c    = idx & 15;
        int k    = idx >> 4;
        int uu   = c >> 2;
        int gate = c & 3;
        int grow = gate * HID + u0 + uu;
        WT[idx] = whh[(size_t)grow * HID + k];
    }
    if (tid < 128) {
        int bb = tid >> 2, uu = tid & 3;
        CS[bb * 4 + uu] = c0[bb * HID + u0 + uu];
    }
    __syncthreads();

    const int b   = tid & 31;   // batch lane for GEMM
    const int ks  = tid >> 5;   // K-slice 0..7
    const int ebb = tid & 31;   // epilogue batch
    const int euu = tid >> 5;   // epilogue unit (valid for tid<128)

    for (int t = 0; t < T_STEPS; t++) {
        const float* hsrc = (t == 0) ? h0 : (out + (size_t)(t - 1) * BATCH * HID);
        // copy h_{t-1} -> HT transposed [k][b] (pad 33, conflict-free)
        for (int i = tid; i < BATCH * HID; i += RTHR) {
            int bb = i >> 9;
            int kk = i & 511;
            HT[kk * 33 + bb] = hsrc[i];
        }
        // prefetch gx for this step
        float gxv[4];
        if (tid < 128) {
            const size_t base = ((size_t)t * BATCH + ebb) * GATES;
#pragma unroll
            for (int g = 0; g < 4; g++)
                gxv[g] = g_gx[base + g * HID + (u0 + euu)];
        }
        __syncthreads();

        // 16 gate-columns per block, packed as 8 f32x2 accumulators
        ull acc2[8];
#pragma unroll
        for (int c = 0; c < 8; c++) acc2[c] = 0ull;

        const float*      hp = HT + (ks * 64) * 33 + b;
        const ulonglong2* wp = (const ulonglong2*)(WT + (ks * 64) * 16);
#pragma unroll 8
        for (int k = 0; k < 64; k++) {
            float hv = *hp; hp += 33;
            ull hd = pk2(hv, hv);
            ulonglong2 q0 = wp[0];
            ulonglong2 q1 = wp[1];
            ulonglong2 q2 = wp[2];
            ulonglong2 q3 = wp[3];
            wp += 4;
            ffma2(acc2[0], hd, q0.x);
            ffma2(acc2[1], hd, q0.y);
            ffma2(acc2[2], hd, q1.x);
            ffma2(acc2[3], hd, q1.y);
            ffma2(acc2[4], hd, q2.x);
            ffma2(acc2[5], hd, q2.y);
            ffma2(acc2[6], hd, q3.x);
            ffma2(acc2[7], hd, q3.y);
        }
        {
            ull* rp = (ull*)(RED + ks * 576 + b * 18);
#pragma unroll
            for (int c = 0; c < 8; c++) rp[c] = acc2[c];
        }
        __syncthreads();

        if (tid < 128) {
            // sum 8 K-slices; pairs (i,f) and (g,o) as f32x2
            const ull* q = (const ull*)(RED + ebb * 18 + euu * 4);
            ull s01 = 0ull, s23 = 0ull;
#pragma unroll
            for (int kq = 0; kq < 8; kq++) {
                s01 = addf2(s01, q[0]);
                s23 = addf2(s23, q[1]);
                q += 288;   // 576 floats = 288 ull
            }
            float2 p01 = upk(s01);
            float2 p23 = upk(s23);
            float iv = p01.x + gxv[0];
            float fv = p01.y + gxv[1];
            float gv = p23.x + gxv[2];
            float ov = p23.y + gxv[3];
            float it = 1.f / (1.f + __expf(-iv));
            float ft = 1.f / (1.f + __expf(-fv));
            float gt = tanhf(gv);
            float ot = 1.f / (1.f + __expf(-ov));
            float cc  = CS[ebb * 4 + euu];
            float cnv = ft * cc + it * gt;
            CS[ebb * 4 + euu] = cnv;
            float hv = ot * tanhf(cnv);
            const int uo = u0 + euu;
            out[(size_t)t * BATCH * HID + ebb * HID + uo] = hv;
            if (t == T_STEPS - 1) {
                hn[ebb * HID + uo] = hv;
                cn[ebb * HID + uo] = cnv;
            }
        }
        if (t < T_STEPS - 1) grid_barrier();
    }
}

// ---------------------------------------------------------------------------
extern "C" void kernel_launch(void* const* d_in, const int* in_sizes, int n_in,
                              void* d_out, int out_size)
{
    const float* x   = (const float*)d_in[0];
    const float* h0  = (const float*)d_in[1];
    const float* c0  = (const float*)d_in[2];
    const float* wih = (const float*)d_in[3];
    const float* bih = (const float*)d_in[4];
    const float* whh = (const float*)d_in[5];
    const float* bhh = (const float*)d_in[6];

    float* out = (float*)d_out;
    float* hn  = out + (size_t)T_STEPS * BATCH * HID;
    float* cn  = hn + BATCH * HID;

    gemm_gx<<<dim3(GATES / 128, (T_STEPS * BATCH) / 128), 256>>>(x, wih, bih, bhh);

    const size_t shmem = SMEM_FLOATS * sizeof(float);
    cudaFuncSetAttribute(lstm_rec, cudaFuncAttributeMaxDynamicSharedMemorySize, (int)shmem);
    lstm_rec<<<RBLK, RTHR, shmem>>>(h0, c0, whh, out, hn, cn);
}

// round 3
// speedup vs baseline: 1.5177x; 1.5072x over previous
#include <cuda_runtime.h>
#include <cstdint>
#include <cstddef>

#define T_STEPS 2048
#define BATCH   32
#define DIM     512
#define HID     512
#define GATES   2048   // 4*HID

typedef unsigned long long ull;

// 512 MB scratch for gx = x @ w_ih^T + b_ih + b_hh
__device__ float g_gx[134217728];  // T_STEPS*BATCH*GATES

// monotonic barrier counter (reset by a tiny kernel each launch)
__device__ unsigned int g_cnt;

// ---------------- packed f32x2 helpers (Blackwell FFMA2 path) ----------------
__device__ __forceinline__ void ffma2(ull& d, ull a, ull b) {
    asm("fma.rn.f32x2 %0, %1, %2, %0;" : "+l"(d) : "l"(a), "l"(b));
}
__device__ __forceinline__ ull addf2(ull a, ull b) {
    ull r; asm("add.rn.f32x2 %0, %1, %2;" : "=l"(r) : "l"(a), "l"(b)); return r;
}
__device__ __forceinline__ ull pk2(float x, float y) {
    ull r; asm("mov.b64 %0, {%1, %2};" : "=l"(r) : "f"(x), "f"(y)); return r;
}
__device__ __forceinline__ float2 upk(ull v) {
    float2 r; asm("mov.b64 {%0, %1}, %2;" : "=f"(r.x), "=f"(r.y) : "l"(v)); return r;
}

// ---------------------------------------------------------------------------
// Kernel 1: gx[r][n] = sum_k X[r][k]*W[n][k] + bih[n] + bhh[n]
//   128x128 tile, 8x8 microtile via FFMA2, K-slab 8, double-buffered smem.
// ---------------------------------------------------------------------------
__global__ void __launch_bounds__(256, 2) gemm_gx(
    const float* __restrict__ X,
    const float* __restrict__ W,
    const float* __restrict__ bih,
    const float* __restrict__ bhh)
{
    __shared__ float As[2][8][128];
    __shared__ float Bs[2][8][128];

    const int bm  = blockIdx.y * 128;
    const int bn  = blockIdx.x * 128;
    const int tid = threadIdx.x;
    const int tx  = tid & 15;
    const int ty  = tid >> 4;

    ull acc2[4][8];
#pragma unroll
    for (int i = 0; i < 4; i++)
#pragma unroll
        for (int j = 0; j < 8; j++) acc2[i][j] = 0ull;

    const int lr = tid >> 1;
    const int lk = (tid & 1) * 4;
    const float* Ap = X + (size_t)(bm + lr) * DIM + lk;
    const float* Bp = W + (size_t)(bn + lr) * DIM + lk;

    {
        float4 av = *(const float4*)Ap;
        float4 bv = *(const float4*)Bp;
        As[0][lk + 0][lr] = av.x; As[0][lk + 1][lr] = av.y;
        As[0][lk + 2][lr] = av.z; As[0][lk + 3][lr] = av.w;
        Bs[0][lk + 0][lr] = bv.x; Bs[0][lk + 1][lr] = bv.y;
        Bs[0][lk + 2][lr] = bv.z; Bs[0][lk + 3][lr] = bv.w;
    }
    __syncthreads();

    const int NSLAB = DIM / 8;
    for (int s = 0; s < NSLAB; s++) {
        const int buf = s & 1;
        float4 avn, bvn;
        if (s + 1 < NSLAB) {
            avn = *(const float4*)(Ap + (s + 1) * 8);
            bvn = *(const float4*)(Bp + (s + 1) * 8);
        }
#pragma unroll
        for (int kk = 0; kk < 8; kk++) {
            const ulonglong2* a01 = (const ulonglong2*)&As[buf][kk][ty * 8];
            ulonglong2 al = a01[0];
            ulonglong2 ah = a01[1];
            ull a2[4] = { al.x, al.y, ah.x, ah.y };
            float4 b0 = *(const float4*)&Bs[buf][kk][tx * 8];
            float4 b1 = *(const float4*)&Bs[buf][kk][tx * 8 + 4];
            ull bd[8] = { pk2(b0.x, b0.x), pk2(b0.y, b0.y),
                          pk2(b0.z, b0.z), pk2(b0.w, b0.w),
                          pk2(b1.x, b1.x), pk2(b1.y, b1.y),
                          pk2(b1.z, b1.z), pk2(b1.w, b1.w) };
#pragma unroll
            for (int i2 = 0; i2 < 4; i2++)
#pragma unroll
                for (int j = 0; j < 8; j++)
                    ffma2(acc2[i2][j], a2[i2], bd[j]);
        }
        if (s + 1 < NSLAB) {
            const int nb = buf ^ 1;
            As[nb][lk + 0][lr] = avn.x; As[nb][lk + 1][lr] = avn.y;
            As[nb][lk + 2][lr] = avn.z; As[nb][lk + 3][lr] = avn.w;
            Bs[nb][lk + 0][lr] = bvn.x; Bs[nb][lk + 1][lr] = bvn.y;
            Bs[nb][lk + 2][lr] = bvn.z; Bs[nb][lk + 3][lr] = bvn.w;
            __syncthreads();
        }
    }

    const int row0 = bm + ty * 8;
    const int col0 = bn + tx * 8;
    float bias[8];
#pragma unroll
    for (int j = 0; j < 8; j++) bias[j] = bih[col0 + j] + bhh[col0 + j];

#pragma unroll
    for (int i = 0; i < 8; i++) {
        const int i2 = i >> 1;
        const int s  = i & 1;
        float v[8];
#pragma unroll
        for (int j = 0; j < 8; j++) {
            float2 p = upk(acc2[i2][j]);
            v[j] = (s ? p.y : p.x) + bias[j];
        }
        float* dst = &g_gx[(size_t)(row0 + i) * GATES + col0];
        float4 v0 = { v[0], v[1], v[2], v[3] };
        float4 v1 = { v[4], v[5], v[6], v[7] };
        *(float4*)dst       = v0;
        *(float4*)(dst + 4) = v1;
    }
}

// ---------------------------------------------------------------------------
// barrier reset (graph-replay safety for the monotonic counter)
// ---------------------------------------------------------------------------
__global__ void reset_cnt() { g_cnt = 0u; }

// ---------------------------------------------------------------------------
// Kernel 2: persistent recurrence. 128 blocks x 256 threads, 1 block/SM.
//   Register-tiled 4x4 microtile: per k one LDS.128(h) + one LDS.128(w).
// ---------------------------------------------------------------------------
#define RBLK 128
#define RTHR 256
// smem floats: WT[512*16]=8192 | HT[512*36]=18432 | RED[8*576]=4608 | CS[128]
#define SMEM_FLOATS (8192 + 18432 + 4608 + 128)

__global__ void __launch_bounds__(RTHR, 1) lstm_rec(
    const float* __restrict__ h0, const float* __restrict__ c0,
    const float* __restrict__ whh,
    float* __restrict__ out, float* __restrict__ hn, float* __restrict__ cn)
{
    extern __shared__ float sm[];
    float* WT  = sm;             // [k:512][c:16]
    float* HT  = sm + 8192;      // [k:512][b:32] pad 36 (16B-aligned rows)
    float* RED = HT + 18432;     // [ks:8][b*18 + c]
    float* CS  = RED + 4608;     // [bb*4+uu]

    const int tid = threadIdx.x;
    const int u0  = blockIdx.x * 4;

    // load w_hh slice: local col c = uu*4+gate <-> global row gate*512 + u0+uu
    for (int idx = tid; idx < 8192; idx += RTHR) {
        int c    = idx & 15;
        int k    = idx >> 4;
        int uu   = c >> 2;
        int gate = c & 3;
        int grow = gate * HID + u0 + uu;
        WT[idx] = whh[(size_t)grow * HID + k];
    }
    if (tid < 128) {
        int bb = tid >> 2, uu = tid & 3;
        CS[bb * 4 + uu] = c0[bb * HID + u0 + uu];
    }
    __syncthreads();

    // GEMM lane mapping: warp = K-slice (64 k), lane: bq (4 batches), cq (4 cols)
    const int ks  = tid >> 5;          // 0..7
    const int ln  = tid & 31;
    const int bq  = ln & 7;            // batches 4bq..4bq+3
    const int cq  = ln >> 3;           // cols 4cq..4cq+3
    const int ebb = tid & 31;          // epilogue batch
    const int euu = tid >> 5;          // epilogue unit (tid<128)

    // gx prefetch for t=0
    float gxv[4];
    if (tid < 128) {
        const size_t base = ((size_t)0 * BATCH + ebb) * GATES;
#pragma unroll
        for (int g = 0; g < 4; g++)
            gxv[g] = g_gx[base + g * HID + (u0 + euu)];
    }

    for (int t = 0; t < T_STEPS; t++) {
        const float* hsrc = (t == 0) ? h0 : (out + (size_t)(t - 1) * BATCH * HID);
        // stage h_{t-1} -> HT transposed [k][b]; coalesced 64B LDG chunks
        for (int i = tid; i < BATCH * HID / 4; i += RTHR) {
            int k4 = (i & 3) | ((i >> 7) << 2);   // 0..127
            int b  = (i >> 2) & 31;
            float4 hv = *(const float4*)(hsrc + b * HID + k4 * 4);
            float* d = HT + (k4 * 4) * 36 + b;
            d[0]   = hv.x;
            d[36]  = hv.y;
            d[72]  = hv.z;
            d[108] = hv.w;
        }
        __syncthreads();

        // 4x4 microtile GEMM: acc2[bb][cp] = cols (4cq+2cp, 4cq+2cp+1)
        ull acc2[4][2];
#pragma unroll
        for (int i = 0; i < 4; i++) { acc2[i][0] = 0ull; acc2[i][1] = 0ull; }

        const float* hp = HT + (ks * 64) * 36 + bq * 4;
        const float* wp = WT + (ks * 64) * 16 + cq * 4;
#pragma unroll 8
        for (int k = 0; k < 64; k++) {
            float4 hv = *(const float4*)hp; hp += 36;
            ulonglong2 wq = *(const ulonglong2*)wp; wp += 16;
            ull h0d = pk2(hv.x, hv.x);
            ull h1d = pk2(hv.y, hv.y);
            ull h2d = pk2(hv.z, hv.z);
            ull h3d = pk2(hv.w, hv.w);
            ffma2(acc2[0][0], h0d, wq.x); ffma2(acc2[0][1], h0d, wq.y);
            ffma2(acc2[1][0], h1d, wq.x); ffma2(acc2[1][1], h1d, wq.y);
            ffma2(acc2[2][0], h2d, wq.x); ffma2(acc2[2][1], h2d, wq.y);
            ffma2(acc2[3][0], h3d, wq.x); ffma2(acc2[3][1], h3d, wq.y);
        }
        // write partials: RED[ks][b:32][c:16 pad 18]
        {
            float* rb = RED + ks * 576;
#pragma unroll
            for (int bb = 0; bb < 4; bb++) {
                ull* rp = (ull*)(rb + (4 * bq + bb) * 18 + 4 * cq);
                rp[0] = acc2[bb][0];
                rp[1] = acc2[bb][1];
            }
        }
        __syncthreads();

        if (tid < 128) {
            const ull* q = (const ull*)(RED + ebb * 18 + euu * 4);
            ull s01 = 0ull, s23 = 0ull;
#pragma unroll
            for (int kq = 0; kq < 8; kq++) {
                s01 = addf2(s01, q[0]);
                s23 = addf2(s23, q[1]);
                q += 288;   // 576 floats
            }
            float2 p01 = upk(s01);
            float2 p23 = upk(s23);
            float iv = p01.x + gxv[0];
            float fv = p01.y + gxv[1];
            float gv = p23.x + gxv[2];
            float ov = p23.y + gxv[3];
            float it = 1.f / (1.f + __expf(-iv));
            float ft = 1.f / (1.f + __expf(-fv));
            float gt = tanhf(gv);
            float ot = 1.f / (1.f + __expf(-ov));
            float cc  = CS[ebb * 4 + euu];
            float cnv = ft * cc + it * gt;
            CS[ebb * 4 + euu] = cnv;
            float hv = ot * tanhf(cnv);
            const int uo = u0 + euu;
            out[(size_t)t * BATCH * HID + ebb * HID + uo] = hv;
            if (t == T_STEPS - 1) {
                hn[ebb * HID + uo] = hv;
                cn[ebb * HID + uo] = cnv;
            }
        }

        // prefetch gx for t+1 (independent of the barrier)
        if (tid < 128 && t + 1 < T_STEPS) {
            const size_t base = ((size_t)(t + 1) * BATCH + ebb) * GATES;
#pragma unroll
            for (int g = 0; g < 4; g++)
                gxv[g] = g_gx[base + g * HID + (u0 + euu)];
        }

        if (t < T_STEPS - 1) {
            // lean release/acquire grid barrier on a monotonic counter
            __syncthreads();
            if (tid == 0) {
                unsigned tgt = (unsigned)(RBLK) * (unsigned)(t + 1);
                asm volatile("red.release.gpu.global.add.u32 [%0], 1;"
                             :: "l"(&g_cnt) : "memory");
                unsigned v;
                do {
                    asm volatile("ld.acquire.gpu.global.u32 %0, [%1];"
                                 : "=r"(v) : "l"(&g_cnt) : "memory");
                } while (v < tgt);
            }
            __syncthreads();
        }
    }
}

// ---------------------------------------------------------------------------
extern "C" void kernel_launch(void* const* d_in, const int* in_sizes, int n_in,
                              void* d_out, int out_size)
{
    const float* x   = (const float*)d_in[0];
    const float* h0  = (const float*)d_in[1];
    const float* c0  = (const float*)d_in[2];
    const float* wih = (const float*)d_in[3];
    const float* bih = (const float*)d_in[4];
    const float* whh = (const float*)d_in[5];
    const float* bhh = (const float*)d_in[6];

    float* out = (float*)d_out;
    float* hn  = out + (size_t)T_STEPS * BATCH * HID;
    float* cn  = hn + BATCH * HID;

    reset_cnt<<<1, 1>>>();
    gemm_gx<<<dim3(GATES / 128, (T_STEPS * BATCH) / 128), 256>>>(x, wih, bih, bhh);

    const size_t shmem = SMEM_FLOATS * sizeof(float);
    cudaFuncSetAttribute(lstm_rec, cudaFuncAttributeMaxDynamicSharedMemorySize, (int)shmem);
    lstm_rec<<<RBLK, RTHR, shmem>>>(h0, c0, whh, out, hn, cn);
}

// round 4
// speedup vs baseline: 1.9372x; 1.2764x over previous
#include <cuda_runtime.h>
#include <cstdint>
#include <cstddef>

#define T_STEPS 2048
#define BATCH   32
#define DIM     512
#define HID     512
#define GATES   2048   // 4*HID

typedef unsigned long long ull;

// 512 MB scratch for gx = x @ w_ih^T + b_ih + b_hh
__device__ float g_gx[134217728];  // T_STEPS*BATCH*GATES

// transposed hidden state h_T[u][b]  (u-major rows of 32 floats = 128 B)
__device__ __align__(16) float g_ht[HID * BATCH];

// monotonic barrier counter (reset by init kernel each launch)
__device__ unsigned int g_cnt;

// ---------------- packed f32x2 helpers (Blackwell FFMA2 path) ----------------
__device__ __forceinline__ void ffma2(ull& d, ull a, ull b) {
    asm("fma.rn.f32x2 %0, %1, %2, %0;" : "+l"(d) : "l"(a), "l"(b));
}
__device__ __forceinline__ ull addf2(ull a, ull b) {
    ull r; asm("add.rn.f32x2 %0, %1, %2;" : "=l"(r) : "l"(a), "l"(b)); return r;
}
__device__ __forceinline__ ull pk2(float x, float y) {
    ull r; asm("mov.b64 %0, {%1, %2};" : "=l"(r) : "f"(x), "f"(y)); return r;
}
__device__ __forceinline__ float2 upk(ull v) {
    float2 r; asm("mov.b64 {%0, %1}, %2;" : "=f"(r.x), "=f"(r.y) : "l"(v)); return r;
}

// ---------------------------------------------------------------------------
// Kernel 1: gx[r][n] = sum_k X[r][k]*W[n][k] + bih[n] + bhh[n]
//   128x128 tile, 8x8 microtile via FFMA2, K-slab 8, double-buffered smem.
// ---------------------------------------------------------------------------
__global__ void __launch_bounds__(256, 2) gemm_gx(
    const float* __restrict__ X,
    const float* __restrict__ W,
    const float* __restrict__ bih,
    const float* __restrict__ bhh)
{
    __shared__ float As[2][8][128];
    __shared__ float Bs[2][8][128];

    const int bm  = blockIdx.y * 128;
    const int bn  = blockIdx.x * 128;
    const int tid = threadIdx.x;
    const int tx  = tid & 15;
    const int ty  = tid >> 4;

    ull acc2[4][8];
#pragma unroll
    for (int i = 0; i < 4; i++)
#pragma unroll
        for (int j = 0; j < 8; j++) acc2[i][j] = 0ull;

    const int lr = tid >> 1;
    const int lk = (tid & 1) * 4;
    const float* Ap = X + (size_t)(bm + lr) * DIM + lk;
    const float* Bp = W + (size_t)(bn + lr) * DIM + lk;

    {
        float4 av = *(const float4*)Ap;
        float4 bv = *(const float4*)Bp;
        As[0][lk + 0][lr] = av.x; As[0][lk + 1][lr] = av.y;
        As[0][lk + 2][lr] = av.z; As[0][lk + 3][lr] = av.w;
        Bs[0][lk + 0][lr] = bv.x; Bs[0][lk + 1][lr] = bv.y;
        Bs[0][lk + 2][lr] = bv.z; Bs[0][lk + 3][lr] = bv.w;
    }
    __syncthreads();

    const int NSLAB = DIM / 8;
    for (int s = 0; s < NSLAB; s++) {
        const int buf = s & 1;
        float4 avn, bvn;
        if (s + 1 < NSLAB) {
            avn = *(const float4*)(Ap + (s + 1) * 8);
            bvn = *(const float4*)(Bp + (s + 1) * 8);
        }
#pragma unroll
        for (int kk = 0; kk < 8; kk++) {
            const ulonglong2* a01 = (const ulonglong2*)&As[buf][kk][ty * 8];
            ulonglong2 al = a01[0];
            ulonglong2 ah = a01[1];
            ull a2[4] = { al.x, al.y, ah.x, ah.y };
            float4 b0 = *(const float4*)&Bs[buf][kk][tx * 8];
            float4 b1 = *(const float4*)&Bs[buf][kk][tx * 8 + 4];
            ull bd[8] = { pk2(b0.x, b0.x), pk2(b0.y, b0.y),
                          pk2(b0.z, b0.z), pk2(b0.w, b0.w),
                          pk2(b1.x, b1.x), pk2(b1.y, b1.y),
                          pk2(b1.z, b1.z), pk2(b1.w, b1.w) };
#pragma unroll
            for (int i2 = 0; i2 < 4; i2++)
#pragma unroll
                for (int j = 0; j < 8; j++)
                    ffma2(acc2[i2][j], a2[i2], bd[j]);
        }
        if (s + 1 < NSLAB) {
            const int nb = buf ^ 1;
            As[nb][lk + 0][lr] = avn.x; As[nb][lk + 1][lr] = avn.y;
            As[nb][lk + 2][lr] = avn.z; As[nb][lk + 3][lr] = avn.w;
            Bs[nb][lk + 0][lr] = bvn.x; Bs[nb][lk + 1][lr] = bvn.y;
            Bs[nb][lk + 2][lr] = bvn.z; Bs[nb][lk + 3][lr] = bvn.w;
            __syncthreads();
        }
    }

    const int row0 = bm + ty * 8;
    const int col0 = bn + tx * 8;
    float bias[8];
#pragma unroll
    for (int j = 0; j < 8; j++) bias[j] = bih[col0 + j] + bhh[col0 + j];

#pragma unroll
    for (int i = 0; i < 8; i++) {
        const int i2 = i >> 1;
        const int s  = i & 1;
        float v[8];
#pragma unroll
        for (int j = 0; j < 8; j++) {
            float2 p = upk(acc2[i2][j]);
            v[j] = (s ? p.y : p.x) + bias[j];
        }
        float* dst = &g_gx[(size_t)(row0 + i) * GATES + col0];
        float4 v0 = { v[0], v[1], v[2], v[3] };
        float4 v1 = { v[4], v[5], v[6], v[7] };
        *(float4*)dst       = v0;
        *(float4*)(dst + 4) = v1;
    }
}

// ---------------------------------------------------------------------------
// init: reset barrier counter + transpose h0 into g_ht[u][b]
// ---------------------------------------------------------------------------
__global__ void init_rec(const float* __restrict__ h0)
{
    int i = blockIdx.x * 256 + threadIdx.x;   // 0..16383
    if (i == 0) g_cnt = 0u;
    int b = i >> 9;
    int u = i & 511;
    g_ht[u * BATCH + b] = h0[i];
}

// ---------------------------------------------------------------------------
// Kernel 2: persistent recurrence. 128 blocks x 256 threads.
//   GEMM reads h_T rows straight from L2 (__ldcg); no smem staging.
// ---------------------------------------------------------------------------
#define RBLK 128
#define RTHR 256
// smem floats: WT[512*16]=8192 | RED[8*576]=4608 | CS[128]
#define SMEM_FLOATS (8192 + 4608 + 128)

__global__ void __launch_bounds__(RTHR, 1) lstm_rec(
    const float* __restrict__ c0,
    const float* __restrict__ whh,
    float* __restrict__ out, float* __restrict__ hn, float* __restrict__ cn)
{
    extern __shared__ float sm[];
    float* WT  = sm;             // [k:512][c:16]
    float* RED = sm + 8192;      // [ks:8][b*18 + c]
    float* CS  = RED + 4608;     // [bb*4+uu]

    const int tid = threadIdx.x;
    const int u0  = blockIdx.x * 4;

    // load w_hh slice: local col c = uu*4+gate <-> global row gate*512 + u0+uu
    for (int idx = tid; idx < 8192; idx += RTHR) {
        int c    = idx & 15;
        int k    = idx >> 4;
        int uu   = c >> 2;
        int gate = c & 3;
        int grow = gate * HID + u0 + uu;
        WT[idx] = whh[(size_t)grow * HID + k];
    }
    if (tid < 128) {
        int bb = tid >> 2, uu = tid & 3;
        CS[bb * 4 + uu] = c0[bb * HID + u0 + uu];
    }
    __syncthreads();

    // GEMM lane mapping: warp = K-slice (64 k), lane: bq (4 batches), cq (4 cols)
    const int ks  = tid >> 5;          // 0..7
    const int ln  = tid & 31;
    const int bq  = ln & 7;            // batches 4bq..4bq+3
    const int cq  = ln >> 3;           // cols 4cq..4cq+3
    const int ebb = tid & 31;          // epilogue batch
    const int euu = tid >> 5;          // epilogue unit (tid<128)

    // gx prefetch for t=0
    float gxv[4];
    if (tid < 128) {
        const size_t base = (size_t)ebb * GATES;
#pragma unroll
        for (int g = 0; g < 4; g++)
            gxv[g] = g_gx[base + g * HID + (u0 + euu)];
    }

    for (int t = 0; t < T_STEPS; t++) {
        // 4x4 microtile GEMM; h rows direct from L2 (fresh via ldcg)
        ull acc2[4][2];
#pragma unroll
        for (int i = 0; i < 4; i++) { acc2[i][0] = 0ull; acc2[i][1] = 0ull; }

        const float4* hp = (const float4*)(g_ht + (ks * 64) * BATCH + bq * 4);
        const float*  wp = WT + (ks * 64) * 16 + cq * 4;
#pragma unroll 16
        for (int k = 0; k < 64; k++) {
            float4 hv = __ldcg(hp); hp += 8;           // +32 floats (one row)
            ulonglong2 wq = *(const ulonglong2*)wp; wp += 16;
            ull h0d = pk2(hv.x, hv.x);
            ull h1d = pk2(hv.y, hv.y);
            ull h2d = pk2(hv.z, hv.z);
            ull h3d = pk2(hv.w, hv.w);
            ffma2(acc2[0][0], h0d, wq.x); ffma2(acc2[0][1], h0d, wq.y);
            ffma2(acc2[1][0], h1d, wq.x); ffma2(acc2[1][1], h1d, wq.y);
            ffma2(acc2[2][0], h2d, wq.x); ffma2(acc2[2][1], h2d, wq.y);
            ffma2(acc2[3][0], h3d, wq.x); ffma2(acc2[3][1], h3d, wq.y);
        }
        // write partials: RED[ks][b:32][c:16 pad 18]
        {
            float* rb = RED + ks * 576;
#pragma unroll
            for (int bb = 0; bb < 4; bb++) {
                ull* rp = (ull*)(rb + (4 * bq + bb) * 18 + 4 * cq);
                rp[0] = acc2[bb][0];
                rp[1] = acc2[bb][1];
            }
        }
        __syncthreads();

        if (tid < 128) {
            const ull* q = (const ull*)(RED + ebb * 18 + euu * 4);
            ull s01 = 0ull, s23 = 0ull;
#pragma unroll
            for (int kq = 0; kq < 8; kq++) {
                s01 = addf2(s01, q[0]);
                s23 = addf2(s23, q[1]);
                q += 288;   // 576 floats
            }
            float2 p01 = upk(s01);
            float2 p23 = upk(s23);
            float iv = p01.x + gxv[0];
            float fv = p01.y + gxv[1];
            float gv = p23.x + gxv[2];
            float ov = p23.y + gxv[3];
            float it = 1.f / (1.f + __expf(-iv));
            float ft = 1.f / (1.f + __expf(-fv));
            float gt = tanhf(gv);
            float ot = 1.f / (1.f + __expf(-ov));
            float cc  = CS[ebb * 4 + euu];
            float cnv = ft * cc + it * gt;
            CS[ebb * 4 + euu] = cnv;
            float hv = ot * tanhf(cnv);
            const int uo = u0 + euu;
            out[(size_t)t * BATCH * HID + ebb * HID + uo] = hv;
            g_ht[uo * BATCH + ebb] = hv;               // transposed copy for next step
            if (t == T_STEPS - 1) {
                hn[ebb * HID + uo] = hv;
                cn[ebb * HID + uo] = cnv;
            }
        }

        // prefetch gx for t+1 (independent of the barrier)
        if (tid < 128 && t + 1 < T_STEPS) {
            const size_t base = ((size_t)(t + 1) * BATCH + ebb) * GATES;
#pragma unroll
            for (int g = 0; g < 4; g++)
                gxv[g] = g_gx[base + g * HID + (u0 + euu)];
        }

        if (t < T_STEPS - 1) {
            // lean release/acquire grid barrier on a monotonic counter
            __syncthreads();
            if (tid == 0) {
                unsigned tgt = (unsigned)(RBLK) * (unsigned)(t + 1);
                asm volatile("red.release.gpu.global.add.u32 [%0], 1;"
                             :: "l"(&g_cnt) : "memory");
                unsigned v;
                do {
                    asm volatile("ld.acquire.gpu.global.u32 %0, [%1];"
                                 : "=r"(v) : "l"(&g_cnt) : "memory");
                } while (v < tgt);
            }
            __syncthreads();
        }
    }
}

// ---------------------------------------------------------------------------
extern "C" void kernel_launch(void* const* d_in, const int* in_sizes, int n_in,
                              void* d_out, int out_size)
{
    const float* x   = (const float*)d_in[0];
    const float* h0  = (const float*)d_in[1];
    const float* c0  = (const float*)d_in[2];
    const float* wih = (const float*)d_in[3];
    const float* bih = (const float*)d_in[4];
    const float* whh = (const float*)d_in[5];
    const float* bhh = (const float*)d_in[6];

    float* out = (float*)d_out;
    float* hn  = out + (size_t)T_STEPS * BATCH * HID;
    float* cn  = hn + BATCH * HID;

    init_rec<<<64, 256>>>(h0);
    gemm_gx<<<dim3(GATES / 128, (T_STEPS * BATCH) / 128), 256>>>(x, wih, bih, bhh);

    const size_t shmem = SMEM_FLOATS * sizeof(float);
    cudaFuncSetAttribute(lstm_rec, cudaFuncAttributeMaxDynamicSharedMemorySize, (int)shmem);
    lstm_rec<<<RBLK, RTHR, shmem>>>(c0, whh, out, hn, cn);
}

// round 5
// speedup vs baseline: 1.9983x; 1.0315x over previous
#include <cuda_runtime.h>
#include <cstdint>
#include <cstddef>

#define T_STEPS 2048
#define BATCH   32
#define DIM     512
#define HID     512
#define GATES   2048   // 4*HID

typedef unsigned long long ull;

// 512 MB scratch for gx = x @ w_ih^T + b_ih + b_hh
__device__ float g_gx[134217728];  // T_STEPS*BATCH*GATES

// double-buffered transposed hidden state h_T[buf][u][b]
__device__ __align__(16) float g_ht[2][HID * BATCH];

// per-chunk monotonic flags: chunk g = h rows [64g, 64g+64), produced by blocks 16g..16g+15
__device__ unsigned int g_cnt[8];

// ---------------- packed f32x2 helpers (Blackwell FFMA2 path) ----------------
__device__ __forceinline__ void ffma2(ull& d, ull a, ull b) {
    asm("fma.rn.f32x2 %0, %1, %2, %0;" : "+l"(d) : "l"(a), "l"(b));
}
__device__ __forceinline__ ull addf2(ull a, ull b) {
    ull r; asm("add.rn.f32x2 %0, %1, %2;" : "=l"(r) : "l"(a), "l"(b)); return r;
}
__device__ __forceinline__ ull pk2(float x, float y) {
    ull r; asm("mov.b64 %0, {%1, %2};" : "=l"(r) : "f"(x), "f"(y)); return r;
}
__device__ __forceinline__ float2 upk(ull v) {
    float2 r; asm("mov.b64 {%0, %1}, %2;" : "=f"(r.x), "=f"(r.y) : "l"(v)); return r;
}

// ---------------------------------------------------------------------------
// Kernel 1: gx[r][n] = sum_k X[r][k]*W[n][k] + bih[n] + bhh[n]
// ---------------------------------------------------------------------------
__global__ void __launch_bounds__(256, 2) gemm_gx(
    const float* __restrict__ X,
    const float* __restrict__ W,
    const float* __restrict__ bih,
    const float* __restrict__ bhh)
{
    __shared__ float As[2][8][128];
    __shared__ float Bs[2][8][128];

    const int bm  = blockIdx.y * 128;
    const int bn  = blockIdx.x * 128;
    const int tid = threadIdx.x;
    const int tx  = tid & 15;
    const int ty  = tid >> 4;

    ull acc2[4][8];
#pragma unroll
    for (int i = 0; i < 4; i++)
#pragma unroll
        for (int j = 0; j < 8; j++) acc2[i][j] = 0ull;

    const int lr = tid >> 1;
    const int lk = (tid & 1) * 4;
    const float* Ap = X + (size_t)(bm + lr) * DIM + lk;
    const float* Bp = W + (size_t)(bn + lr) * DIM + lk;

    {
        float4 av = *(const float4*)Ap;
        float4 bv = *(const float4*)Bp;
        As[0][lk + 0][lr] = av.x; As[0][lk + 1][lr] = av.y;
        As[0][lk + 2][lr] = av.z; As[0][lk + 3][lr] = av.w;
        Bs[0][lk + 0][lr] = bv.x; Bs[0][lk + 1][lr] = bv.y;
        Bs[0][lk + 2][lr] = bv.z; Bs[0][lk + 3][lr] = bv.w;
    }
    __syncthreads();

    const int NSLAB = DIM / 8;
    for (int s = 0; s < NSLAB; s++) {
        const int buf = s & 1;
        float4 avn, bvn;
        if (s + 1 < NSLAB) {
            avn = *(const float4*)(Ap + (s + 1) * 8);
            bvn = *(const float4*)(Bp + (s + 1) * 8);
        }
#pragma unroll
        for (int kk = 0; kk < 8; kk++) {
            const ulonglong2* a01 = (const ulonglong2*)&As[buf][kk][ty * 8];
            ulonglong2 al = a01[0];
            ulonglong2 ah = a01[1];
            ull a2[4] = { al.x, al.y, ah.x, ah.y };
            float4 b0 = *(const float4*)&Bs[buf][kk][tx * 8];
            float4 b1 = *(const float4*)&Bs[buf][kk][tx * 8 + 4];
            ull bd[8] = { pk2(b0.x, b0.x), pk2(b0.y, b0.y),
                          pk2(b0.z, b0.z), pk2(b0.w, b0.w),
                          pk2(b1.x, b1.x), pk2(b1.y, b1.y),
                          pk2(b1.z, b1.z), pk2(b1.w, b1.w) };
#pragma unroll
            for (int i2 = 0; i2 < 4; i2++)
#pragma unroll
                for (int j = 0; j < 8; j++)
                    ffma2(acc2[i2][j], a2[i2], bd[j]);
        }
        if (s + 1 < NSLAB) {
            const int nb = buf ^ 1;
            As[nb][lk + 0][lr] = avn.x; As[nb][lk + 1][lr] = avn.y;
            As[nb][lk + 2][lr] = avn.z; As[nb][lk + 3][lr] = avn.w;
            Bs[nb][lk + 0][lr] = bvn.x; Bs[nb][lk + 1][lr] = bvn.y;
            Bs[nb][lk + 2][lr] = bvn.z; Bs[nb][lk + 3][lr] = bvn.w;
            __syncthreads();
        }
    }

    const int row0 = bm + ty * 8;
    const int col0 = bn + tx * 8;
    float bias[8];
#pragma unroll
    for (int j = 0; j < 8; j++) bias[j] = bih[col0 + j] + bhh[col0 + j];

#pragma unroll
    for (int i = 0; i < 8; i++) {
        const int i2 = i >> 1;
        const int s  = i & 1;
        float v[8];
#pragma unroll
        for (int j = 0; j < 8; j++) {
            float2 p = upk(acc2[i2][j]);
            v[j] = (s ? p.y : p.x) + bias[j];
        }
        float* dst = &g_gx[(size_t)(row0 + i) * GATES + col0];
        float4 v0 = { v[0], v[1], v[2], v[3] };
        float4 v1 = { v[4], v[5], v[6], v[7] };
        *(float4*)dst       = v0;
        *(float4*)(dst + 4) = v1;
    }
}

// ---------------------------------------------------------------------------
// init: reset chunk flags + transpose h0 into g_ht[1][u][b]  (step 0 reads buf 1)
// ---------------------------------------------------------------------------
__global__ void init_rec(const float* __restrict__ h0)
{
    int i = blockIdx.x * 256 + threadIdx.x;   // 0..16383
    if (i < 8) g_cnt[i] = 0u;
    int b = i >> 9;
    int u = i & 511;
    g_ht[1][u * BATCH + b] = h0[i];
}

// ---------------------------------------------------------------------------
// Kernel 2: persistent recurrence. 128 blocks x 256 threads.
//   Per-warp chunk-flag sync + double-buffered h; h read from L2 (__ldcg).
// ---------------------------------------------------------------------------
#define RBLK 128
#define RTHR 256
// smem floats: WT[512*16]=8192 | RED[8*576]=4608 | CS[128]
#define SMEM_FLOATS (8192 + 4608 + 128)

__global__ void __launch_bounds__(RTHR, 1) lstm_rec(
    const float* __restrict__ c0,
    const float* __restrict__ whh,
    float* __restrict__ out, float* __restrict__ hn, float* __restrict__ cn)
{
    extern __shared__ float sm[];
    float* WT  = sm;             // [k:512][c:16]
    float* RED = sm + 8192;      // [ks:8][b*18 + c]
    float* CS  = RED + 4608;     // [bb*4+uu]

    const int tid = threadIdx.x;
    const int u0  = blockIdx.x * 4;
    const int my_chunk = blockIdx.x >> 4;     // chunk this block produces

    // load w_hh slice: local col c = uu*4+gate <-> global row gate*512 + u0+uu
    for (int idx = tid; idx < 8192; idx += RTHR) {
        int c    = idx & 15;
        int k    = idx >> 4;
        int uu   = c >> 2;
        int gate = c & 3;
        int grow = gate * HID + u0 + uu;
        WT[idx] = whh[(size_t)grow * HID + k];
    }
    if (tid < 128) {
        int bb = tid >> 2, uu = tid & 3;
        CS[bb * 4 + uu] = c0[bb * HID + u0 + uu];
    }
    __syncthreads();

    // GEMM lane mapping: warp = K-slice (64 k), lane: bq (4 batches), cq (4 cols)
    const int ks  = tid >> 5;          // 0..7  (also = chunk this warp consumes)
    const int ln  = tid & 31;
    const int bq  = ln & 7;            // batches 4bq..4bq+3
    const int cq  = ln >> 3;           // cols 4cq..4cq+3
    const int ebb = tid & 31;          // epilogue batch
    const int euu = tid >> 5;          // epilogue unit (tid<128)

    // gx prefetch for t=0
    float gxv[4];
    if (tid < 128) {
        const size_t base = (size_t)ebb * GATES;
#pragma unroll
        for (int g = 0; g < 4; g++)
            gxv[g] = g_gx[base + g * HID + (u0 + euu)];
    }

    for (int t = 0; t < T_STEPS; t++) {
        const int rb = (t & 1) ^ 1;    // read buffer (h_{t-1})
        const int wb = t & 1;          // write buffer (h_t)

        // per-warp chunk wait: h_{t-1} rows 64ks.. ready when g_cnt[ks] >= 16*t
        if (t > 0) {
            if (ln == 0) {
                const unsigned tgt = 16u * (unsigned)t;
                unsigned v;
                do {
                    asm volatile("ld.acquire.gpu.global.u32 %0, [%1];"
                                 : "=r"(v) : "l"(&g_cnt[ks]) : "memory");
                } while (v < tgt);
            }
            __syncwarp();
        }

        // 4x4 microtile GEMM; h rows direct from L2 (fresh via ldcg)
        ull acc2[4][2];
#pragma unroll
        for (int i = 0; i < 4; i++) { acc2[i][0] = 0ull; acc2[i][1] = 0ull; }

        const float4* hp = (const float4*)(g_ht[rb] + (ks * 64) * BATCH + bq * 4);
        const float*  wp = WT + (ks * 64) * 16 + cq * 4;
#pragma unroll 16
        for (int k = 0; k < 64; k++) {
            float4 hv = __ldcg(hp); hp += 8;           // +32 floats (one row)
            ulonglong2 wq = *(const ulonglong2*)wp; wp += 16;
            ull h0d = pk2(hv.x, hv.x);
            ull h1d = pk2(hv.y, hv.y);
            ull h2d = pk2(hv.z, hv.z);
            ull h3d = pk2(hv.w, hv.w);
            ffma2(acc2[0][0], h0d, wq.x); ffma2(acc2[0][1], h0d, wq.y);
            ffma2(acc2[1][0], h1d, wq.x); ffma2(acc2[1][1], h1d, wq.y);
            ffma2(acc2[2][0], h2d, wq.x); ffma2(acc2[2][1], h2d, wq.y);
            ffma2(acc2[3][0], h3d, wq.x); ffma2(acc2[3][1], h3d, wq.y);
        }
        // write partials: RED[ks][b:32][c:16 pad 18]
        {
            float* rbuf = RED + ks * 576;
#pragma unroll
            for (int bb = 0; bb < 4; bb++) {
                ull* rp = (ull*)(rbuf + (4 * bq + bb) * 18 + 4 * cq);
                rp[0] = acc2[bb][0];
                rp[1] = acc2[bb][1];
            }
        }
        __syncthreads();

        if (tid < 128) {
            const ull* q = (const ull*)(RED + ebb * 18 + euu * 4);
            ull s01 = 0ull, s23 = 0ull;
#pragma unroll
            for (int kq = 0; kq < 8; kq++) {
                s01 = addf2(s01, q[0]);
                s23 = addf2(s23, q[1]);
                q += 288;   // 576 floats
            }
            float2 p01 = upk(s01);
            float2 p23 = upk(s23);
            float iv = p01.x + gxv[0];
            float fv = p01.y + gxv[1];
            float gv = p23.x + gxv[2];
            float ov = p23.y + gxv[3];
            float it = 1.f / (1.f + __expf(-iv));
            float ft = 1.f / (1.f + __expf(-fv));
            float gt = tanhf(gv);
            float ot = 1.f / (1.f + __expf(-ov));
            float cc  = CS[ebb * 4 + euu];
            float cnv = ft * cc + it * gt;
            CS[ebb * 4 + euu] = cnv;
            float hv = ot * tanhf(cnv);
            const int uo = u0 + euu;
            g_ht[wb][uo * BATCH + ebb] = hv;           // publish h_t (transposed)
            out[(size_t)t * BATCH * HID + ebb * HID + uo] = hv;
            if (t == T_STEPS - 1) {
                hn[ebb * HID + uo] = hv;
                cn[ebb * HID + uo] = cnv;
            }
        }

        // all epilogue stores done block-wide, then release this block's chunk
        __syncthreads();
        if (tid == 0 && t < T_STEPS - 1) {
            asm volatile("red.release.gpu.global.add.u32 [%0], 1;"
                         :: "l"(&g_cnt[my_chunk]) : "memory");
        }

        // prefetch gx for t+1 (overlaps with other blocks' progress)
        if (tid < 128 && t + 1 < T_STEPS) {
            const size_t base = ((size_t)(t + 1) * BATCH + ebb) * GATES;
#pragma unroll
            for (int g = 0; g < 4; g++)
                gxv[g] = g_gx[base + g * HID + (u0 + euu)];
        }
    }
}

// ---------------------------------------------------------------------------
extern "C" void kernel_launch(void* const* d_in, const int* in_sizes, int n_in,
                              void* d_out, int out_size)
{
    const float* x   = (const float*)d_in[0];
    const float* h0  = (const float*)d_in[1];
    const float* c0  = (const float*)d_in[2];
    const float* wih = (const float*)d_in[3];
    const float* bih = (const float*)d_in[4];
    const float* whh = (const float*)d_in[5];
    const float* bhh = (const float*)d_in[6];

    float* out = (float*)d_out;
    float* hn  = out + (size_t)T_STEPS * BATCH * HID;
    float* cn  = hn + BATCH * HID;

    init_rec<<<64, 256>>>(h0);
    gemm_gx<<<dim3(GATES / 128, (T_STEPS * BATCH) / 128), 256>>>(x, wih, bih, bhh);

    const size_t shmem = SMEM_FLOATS * sizeof(float);
    cudaFuncSetAttribute(lstm_rec, cudaFuncAttributeMaxDynamicSharedMemorySize, (int)shmem);
    lstm_rec<<<RBLK, RTHR, shmem>>>(c0, whh, out, hn, cn);
}